// round 7
// baseline (speedup 1.0000x reference)
#include <cuda_runtime.h>

#define N     4096
#define NJ    64            // j-chunks
#define JC    (N / NJ)      // 64 j per chunk
#define IB    256           // i per pairwise block (1 per thread)
#define NBI   (N / IB)      // 16 i-blocks
#define NSORT 6             // sorter blocks (features with closed forms)

// Pairwise partials (sky, mass_sim) per j-chunk, fixed order => deterministic
__device__ float2 g_part2[NJ][N];
// Closed-form per-row sums: [0]=dt [1]=dpsi [2]=dra [3]=ddec [4]=freq_ov [5]=dist_ratio
__device__ float  g_closed[NSORT][N];

__device__ __forceinline__ float f_ex2(float x) {
    float r; asm("ex2.approx.ftz.f32 %0, %1;" : "=f"(r) : "f"(x)); return r;
}
__device__ __forceinline__ float f_lg2(float x) {
    float r; asm("lg2.approx.ftz.f32 %0, %1;" : "=f"(r) : "f"(x)); return r;
}
__device__ __forceinline__ float f_rcp(float x) {
    float r; asm("rcp.approx.ftz.f32 %0, %1;" : "=f"(r) : "f"(x)); return r;
}
__device__ __forceinline__ float f_sqrt(float x) {
    float r; asm("sqrt.approx.ftz.f32 %0, %1;" : "=f"(r) : "f"(x)); return r;
}

// mc30 = chirp_mass/30 (pairwise mass_sim needs it)
__device__ __forceinline__ float3 pair_inv(const float* __restrict__ p, int idx) {
    const float* q = p + idx * 15;
    float m1 = q[0] * 95.0f + 5.0f;
    float m2 = q[1] * 95.0f + 5.0f;
    float mc = f_ex2(0.6f * f_lg2(m1 * m2) - 0.2f * f_lg2(m1 + m2));
    return make_float3(q[3], q[4], mc * (1.0f / 30.0f));   // ra, dec, mc30
}

// Sort keys per feature
__device__ __forceinline__ float sort_key(const float* __restrict__ p, int e, int feat) {
    const float* q = p + e * 15;
    switch (feat) {
        case 0: return q[5];                         // t
        case 1: return q[7];                         // psi
        case 2: return q[3];                         // ra
        case 3: return q[4];                         // dec
        case 4: {                                    // F = fisco*log2e/100
            float msum = (q[0] * 95.0f + 5.0f) + (q[1] * 95.0f + 5.0f);
            const float C = 220.0f * 1.4426950408889634f * 0.01f;
            return C * f_rcp(msum);
        }
        default: return f_lg2(q[2] * 2950.0f + 50.0f);   // L = log2(dist)
    }
}

// shared memory union (sorter needs 4096 float2 = 32KB; pairwise needs 1KB)
#define SMEM_BYTES (4096 * 8 + 256 * 8 + 64 + 16)

__global__ void __launch_bounds__(IB) fused_kernel(const float* __restrict__ p) {
    __shared__ __align__(16) unsigned char smraw[SMEM_BYTES];
    const int tid = threadIdx.x;

    if (blockIdx.x < NSORT) {
        // ================= SORTER BLOCK: feature = blockIdx.x =================
        const int feat = blockIdx.x;
        const bool is_exp = (feat >= 4);
        float2* s    = reinterpret_cast<float2*>(smraw);            // [4096] key,idx
        float2* seg  = reinterpret_cast<float2*>(smraw + 32768);    // [256]
        float2* wsum = reinterpret_cast<float2*>(smraw + 32768 + 2048); // [8]
        float2* stot = reinterpret_cast<float2*>(smraw + 32768 + 2048 + 64);

        // load keys
        #pragma unroll
        for (int q = 0; q < 16; ++q) {
            int e = tid + 256 * q;
            s[e] = make_float2(sort_key(p, e, feat), (float)e);
        }

        // bitonic sort (4096), 78 substeps
        for (int k2 = 2; k2 <= 4096; k2 <<= 1) {
            for (int jj = k2 >> 1; jj > 0; jj >>= 1) {
                __syncthreads();
                #pragma unroll
                for (int q = 0; q < 8; ++q) {
                    int pp = tid + 256 * q;              // 0..2047
                    int lowb = pp & (jj - 1);
                    int ii = ((pp ^ lowb) << 1) | lowb;
                    int pa = ii | jj;
                    float2 A = s[ii], B = s[pa];
                    bool up = ((ii & k2) == 0);
                    if ((A.x > B.x) == up) { s[ii] = B; s[pa] = A; }
                }
            }
        }
        __syncthreads();

        // segmented scan: thread owns 16 consecutive sorted elements
        const int base = tid * 16;
        float2 run = make_float2(0.f, 0.f);
        for (int q = 0; q < 16; ++q) {
            float kk = s[base + q].x;
            if (is_exp) { run.x += f_ex2(kk); run.y += f_ex2(-kk); }
            else        { run.x += kk; }
        }
        seg[tid] = run;
        __syncthreads();

        // block-level exclusive scan of seg[256]
        {
            const int lane = tid & 31, wid = tid >> 5;
            float2 v = seg[tid];
            #pragma unroll
            for (int off = 1; off < 32; off <<= 1) {
                float ax = __shfl_up_sync(0xFFFFFFFFu, v.x, off);
                float ay = __shfl_up_sync(0xFFFFFFFFu, v.y, off);
                if (lane >= off) { v.x += ax; v.y += ay; }
            }
            if (lane == 31) wsum[wid] = v;
            __syncthreads();
            if (tid < 8) {
                float2 w = wsum[tid];
                #pragma unroll
                for (int off = 1; off < 8; off <<= 1) {
                    float ax = __shfl_up_sync(0xFFu, w.x, off);
                    float ay = __shfl_up_sync(0xFFu, w.y, off);
                    if ((tid & 7) >= off) { w.x += ax; w.y += ay; }
                }
                wsum[tid] = w;
                if (tid == 7) *stot = w;   // grand totals
            }
            __syncthreads();
            float2 excl = make_float2(v.x - seg[tid].x, v.y - seg[tid].y);
            if (wid > 0) { excl.x += wsum[wid - 1].x; excl.y += wsum[wid - 1].y; }
            seg[tid] = excl;               // exclusive prefix at segment start
        }
        __syncthreads();

        const float Stot = stot->x;
        const float Wtot = stot->y;
        float2 run2 = seg[tid];
        for (int q = 0; q < 16; ++q) {
            int e = base + q;
            float kk  = s[e].x;
            int  idx  = (int)s[e].y;
            float res;
            if (is_exp) {
                float u = f_ex2(kk), w = f_ex2(-kk);
                // sum_j 2^{-|k-kj|} = 2^{-k}*(prefix incl of 2^{kj}) + 2^{k}*(suffix of 2^{-kj})
                res = w * (run2.x + u) + u * (Wtot - run2.y - w);
                run2.x += u; run2.y += w;
            } else {
                // sum_j |k - kj| = 2*(k*rank - prefix) + S - n*k
                res = 2.0f * (kk * (float)e - run2.x) + Stot - (float)N * kk;
                run2.x += kk;
            }
            g_closed[feat][idx] = res;
        }
        return;
    }

    // ================= PAIRWISE BLOCK: sky_sep + mass_sim only =================
    float4* sj = reinterpret_cast<float4*>(smraw);   // [JC] {ra, dec, mc30, 0}
    const int pb = blockIdx.x - NSORT;
    const int ib = pb & (NBI - 1);
    const int jb = pb >> 4;                // NBI = 16
    const int i  = ib * IB + tid;
    const int j0 = jb * JC;

    if (tid < JC) {
        float3 v = pair_inv(p, j0 + tid);
        sj[tid] = make_float4(v.x, v.y, v.z, 0.f);
    }
    float3 a = pair_inv(p, i);
    __syncthreads();

    float s_sky = 0.f, s_ms = 0.f;
    #pragma unroll 8
    for (int j = 0; j < JC; ++j) {
        const float4 b = sj[j];
        float dra = a.x - b.x;
        float dde = a.y - b.y;
        s_sky += f_sqrt(fmaf(dra, dra, dde * dde));
        s_ms  += f_rcp(1.0f + fabsf(a.z - b.z));
    }
    g_part2[jb][i] = make_float2(s_sky, s_ms);
}

// ---------------------------------------------------------------------------
// Finish: 8 lanes per row; 128 blocks x 256 threads.
// ---------------------------------------------------------------------------
#define FTB 256
__global__ void __launch_bounds__(FTB) finish_kernel(
    const float* __restrict__ W1, const float* __restrict__ b1,
    const float* __restrict__ ln_g, const float* __restrict__ ln_b,
    const float* __restrict__ W2, const float* __restrict__ b2,
    float* __restrict__ out)
{
    __shared__ float sW1[8 * 32];
    __shared__ float sW2[32 * 16];
    __shared__ float sb1[32], sg[32], sbeta[32], sb2[16];

    for (int k = threadIdx.x; k < 256; k += FTB) sW1[k] = W1[k];
    for (int k = threadIdx.x; k < 512; k += FTB) sW2[k] = W2[k];
    if (threadIdx.x < 32) {
        int k = threadIdx.x;
        sb1[k] = b1[k]; sg[k] = ln_g[k]; sbeta[k] = ln_b[k];
        if (k < 16) sb2[k] = b2[k];
    }
    __syncthreads();

    const int lane = threadIdx.x & 31;
    const int warp = threadIdx.x >> 5;
    const int sub  = lane & 7;
    const int rig  = lane >> 3;
    const int i    = blockIdx.x * 32 + warp * 4 + rig;

    // reduce pairwise partials: lane sums 8 of 64 chunks, butterfly
    float t_sky = 0.f, t_ms = 0.f;
    #pragma unroll
    for (int cc = 0; cc < 8; ++cc) {
        float2 pp = g_part2[sub * 8 + cc][i];
        t_sky += pp.x; t_ms += pp.y;
    }
    #pragma unroll
    for (int m = 1; m < 8; m <<= 1) {
        t_sky += __shfl_xor_sync(0xFFFFFFFFu, t_sky, m);
        t_ms  += __shfl_xor_sync(0xFFFFFFFFu, t_ms,  m);
    }

    const float inv = 1.0f / (float)(N - 1);
    float x[8];
    x[0] = g_closed[0][i] * inv;                 // dt
    x[1] = t_sky * inv;                          // sky_sep (self=0)
    x[2] = (t_ms - 1.0f) * inv;                  // mass_sim (self=1)
    x[3] = (g_closed[4][i] - 1.0f) * inv;        // freq_ov  (self~1)
    x[4] = (g_closed[5][i] - 1.0f) * inv;        // dist_ratio (self~1)
    x[5] = g_closed[1][i] * inv;                 // dpsi
    x[6] = g_closed[2][i] * inv;                 // dra
    x[7] = g_closed[3][i] * inv;                 // ddec

    const int k0 = sub * 4;
    float h[4];
    #pragma unroll
    for (int kk = 0; kk < 4; ++kk) {
        float acc = sb1[k0 + kk];
        #pragma unroll
        for (int f = 0; f < 8; ++f)
            acc = fmaf(x[f], sW1[f * 32 + k0 + kk], acc);
        h[kk] = acc;
    }

    float s1 = h[0] + h[1] + h[2] + h[3];
    #pragma unroll
    for (int m = 1; m < 8; m <<= 1) s1 += __shfl_xor_sync(0xFFFFFFFFu, s1, m);
    float mu = s1 * (1.0f / 32.0f);

    float s2 = 0.f;
    #pragma unroll
    for (int kk = 0; kk < 4; ++kk) {
        float d = h[kk] - mu;
        s2 = fmaf(d, d, s2);
    }
    #pragma unroll
    for (int m = 1; m < 8; m <<= 1) s2 += __shfl_xor_sync(0xFFFFFFFFu, s2, m);
    float rs = rsqrtf(s2 * (1.0f / 32.0f) + 1e-5f);

    #pragma unroll
    for (int kk = 0; kk < 4; ++kk) {
        float v = fmaf((h[kk] - mu) * rs, sg[k0 + kk], sbeta[k0 + kk]);
        h[kk] = 0.5f * v * (1.0f + erff(v * 0.7071067811865475f));
    }

    float o[16];
    #pragma unroll
    for (int oo = 0; oo < 16; ++oo) o[oo] = 0.f;
    #pragma unroll
    for (int kk = 0; kk < 4; ++kk) {
        #pragma unroll
        for (int oo = 0; oo < 16; ++oo)
            o[oo] = fmaf(h[kk], sW2[(k0 + kk) * 16 + oo], o[oo]);
    }
    #pragma unroll
    for (int m = 1; m < 8; m <<= 1) {
        #pragma unroll
        for (int oo = 0; oo < 16; ++oo)
            o[oo] += __shfl_xor_sync(0xFFFFFFFFu, o[oo], m);
    }

    if (sub == 0) {
        float4* op = reinterpret_cast<float4*>(out + i * 16);
        op[0] = make_float4(o[0]  + sb2[0],  o[1]  + sb2[1],
                            o[2]  + sb2[2],  o[3]  + sb2[3]);
        op[1] = make_float4(o[4]  + sb2[4],  o[5]  + sb2[5],
                            o[6]  + sb2[6],  o[7]  + sb2[7]);
        op[2] = make_float4(o[8]  + sb2[8],  o[9]  + sb2[9],
                            o[10] + sb2[10], o[11] + sb2[11]);
        op[3] = make_float4(o[12] + sb2[12], o[13] + sb2[13],
                            o[14] + sb2[14], o[15] + sb2[15]);
    }
}

extern "C" void kernel_launch(void* const* d_in, const int* in_sizes, int n_in,
                              void* d_out, int out_size) {
    const float* params = (const float*)d_in[0];
    const float* W1     = (const float*)d_in[1];
    const float* b1     = (const float*)d_in[2];
    const float* ln_g   = (const float*)d_in[3];
    const float* ln_b   = (const float*)d_in[4];
    const float* W2     = (const float*)d_in[5];
    const float* b2     = (const float*)d_in[6];
    float* out = (float*)d_out;

    fused_kernel<<<NSORT + NBI * NJ, IB>>>(params);
    finish_kernel<<<N * 8 / FTB, FTB>>>(W1, b1, ln_g, ln_b, W2, b2, out);
}

// round 8
// speedup vs baseline: 1.2281x; 1.2281x over previous
#include <cuda_runtime.h>

#define N      4096
#define NJ     32            // j-chunks (pairwise)
#define JC     128           // j per chunk
#define IB     256           // threads per block
#define NBI    16            // i-blocks
#define NFEAT  6
#define NB     256           // value buckets per feature

// Pairwise partials (sky_sep, mass_sim) per j-chunk
__device__ float2 g_part2[NJ][N];
// Closed-form per-row sums: 0=dt 1=dpsi 2=dra 3=ddec 4=freq_ov 5=dist_ratio
__device__ float  g_closed[NFEAT][N];

__device__ __forceinline__ float f_ex2(float x) {
    float r; asm("ex2.approx.ftz.f32 %0, %1;" : "=f"(r) : "f"(x)); return r;
}
__device__ __forceinline__ float f_lg2(float x) {
    float r; asm("lg2.approx.ftz.f32 %0, %1;" : "=f"(r) : "f"(x)); return r;
}
__device__ __forceinline__ float f_rcp(float x) {
    float r; asm("rcp.approx.ftz.f32 %0, %1;" : "=f"(r) : "f"(x)); return r;
}
__device__ __forceinline__ float f_sqrt(float x) {
    float r; asm("sqrt.approx.ftz.f32 %0, %1;" : "=f"(r) : "f"(x)); return r;
}

// pairwise needs (ra, dec, mc30)
__device__ __forceinline__ float3 pair_inv(const float* __restrict__ p, int idx) {
    const float* q = p + idx * 15;
    float m1 = q[0] * 95.0f + 5.0f;
    float m2 = q[1] * 95.0f + 5.0f;
    float mc = f_ex2(0.6f * f_lg2(m1 * m2) - 0.2f * f_lg2(m1 + m2));
    return make_float3(q[3], q[4], mc * (1.0f / 30.0f));
}

// Per feature: v = monotone bucket variable; (u, w) such that for j "below" i
// (v_j in lower bucket) the pair term is w_i*u_j, for j "above" it's u_i*w_j,
// within-bucket it's min(u_i*w_j, u_j*w_i). For abs features u = key.
__device__ __forceinline__ void feat_vals(const float* __restrict__ p, int e, int feat,
                                          float& v, float& u, float& w) {
    const float* q = p + e * 15;
    if (feat == 0)      { v = q[5]; u = v; w = 0.f; }
    else if (feat == 1) { v = q[7]; u = v; w = 0.f; }
    else if (feat == 2) { v = q[3]; u = v; w = 0.f; }
    else if (feat == 3) { v = q[4]; u = v; w = 0.f; }
    else if (feat == 4) {
        // freq_ov: x = (220/msum)*log2(e)/100; bucket by msum (monotone, uniform-ish)
        // below in msum => x_j > x_i => term 2^{x_i-x_j} = w_i*u_j with u=2^{-x}, w=2^{x}
        float msum = (q[0] + q[1]) * 95.0f + 10.0f;
        const float C = 3.1739290899557192f;   // 220*log2(e)/100
        float x = C * f_rcp(msum);
        v = msum; u = f_ex2(-x); w = f_ex2(x);
    } else {
        // dist_ratio: bucket by dist; below => d_j<d_i => term d_j/d_i = w_i*u_j
        float d = q[2] * 2950.0f + 50.0f;
        v = d; u = d; w = f_rcp(d);
    }
}

// exclusive prefix over 256 threads (tid order); all 256 threads must call.
__device__ __forceinline__ float excl_scan256(float val, float* warpTmp) {
    const int lane = threadIdx.x & 31, wid = threadIdx.x >> 5;
    float incl = val;
    #pragma unroll
    for (int off = 1; off < 32; off <<= 1) {
        float t = __shfl_up_sync(0xFFFFFFFFu, incl, off);
        if (lane >= off) incl += t;
    }
    __syncthreads();                    // protect warpTmp from previous call's readers
    if (lane == 31) warpTmp[wid] = incl;
    __syncthreads();
    float base = 0.f;
    #pragma unroll
    for (int ww = 0; ww < 8; ++ww)
        base += (ww < wid) ? warpTmp[ww] : 0.f;
    return base + incl - val;
}

// smem layout (48208 B <= 48KB static limit); pairwise blocks alias the front.
#define OFF_U     0
#define OFF_W     16384
#define OFF_IDX   32768
#define OFF_START 40960
#define OFF_CNT   42000
#define OFF_CUR   43024
#define OFF_AGGU  44048
#define OFF_AGGW  45072
#define OFF_PU    46096
#define OFF_REV   47120
#define OFF_WTMP  48144
#define SMEM_SZ   48208

__global__ void __launch_bounds__(IB) fused_kernel(const float* __restrict__ p) {
    __shared__ __align__(16) unsigned char smraw[SMEM_SZ];
    const int tid = threadIdx.x;

    if (blockIdx.x < NFEAT) {
        // ================= FEATURE BLOCK (bucketed closed form) =================
        const int feat = blockIdx.x;
        const bool isexp = (feat >= 4);
        float*          s_u     = (float*)(smraw + OFF_U);
        float*          s_w     = (float*)(smraw + OFF_W);
        unsigned short* s_idx   = (unsigned short*)(smraw + OFF_IDX);
        int*            s_start = (int*)(smraw + OFF_START);   // [257]
        int*            s_cnt   = (int*)(smraw + OFF_CNT);
        int*            s_cur   = (int*)(smraw + OFF_CUR);
        float*          s_aggU  = (float*)(smraw + OFF_AGGU);
        float*          s_aggW  = (float*)(smraw + OFF_AGGW);
        float*          s_pU    = (float*)(smraw + OFF_PU);
        float*          s_rev   = (float*)(smraw + OFF_REV);
        float*          warpTmp = (float*)(smraw + OFF_WTMP);

        float lo, scale;
        if      (feat == 4) { lo = 10.0f; scale = 256.0f / 190.0f; }
        else if (feat == 5) { lo = 50.0f; scale = 256.0f / 2950.0f; }
        else                { lo = 0.0f;  scale = 256.0f; }

        s_cnt[tid] = 0; s_cur[tid] = 0; s_aggU[tid] = 0.f; s_aggW[tid] = 0.f;
        __syncthreads();

        // pass 1: bucket counts + aggregates
        for (int e = tid; e < N; e += IB) {
            float v, u, w; feat_vals(p, e, feat, v, u, w);
            int b = (int)((v - lo) * scale);
            b = min(NB - 1, max(0, b));
            atomicAdd(&s_cnt[b], 1);
            atomicAdd(&s_aggU[b], u);
            if (isexp) atomicAdd(&s_aggW[b], w);
        }
        __syncthreads();

        // scans: bucket starts, below-prefix of U, above-suffix (U for abs, W for exp)
        float e0 = excl_scan256((float)s_cnt[tid], warpTmp);
        float pu = excl_scan256(s_aggU[tid], warpTmp);
        float rv = excl_scan256(isexp ? s_aggW[NB - 1 - tid] : s_aggU[NB - 1 - tid], warpTmp);
        __syncthreads();
        s_start[tid] = (int)e0;
        if (tid == NB - 1) s_start[NB] = N;
        s_pU[tid] = pu;
        s_rev[NB - 1 - tid] = rv;
        __syncthreads();

        // pass 2: counting-sort scatter
        for (int e = tid; e < N; e += IB) {
            float v, u, w; feat_vals(p, e, feat, v, u, w);
            int b = (int)((v - lo) * scale);
            b = min(NB - 1, max(0, b));
            int pos = s_start[b] + atomicAdd(&s_cur[b], 1);
            s_u[pos] = u; s_w[pos] = w; s_idx[pos] = (unsigned short)e;
        }
        __syncthreads();

        // pass 3: per element = cross-bucket closed form + exact within-bucket
        for (int e = tid * 16; e < tid * 16 + 16; ++e) {
            int b = 0;
            #pragma unroll
            for (int s = 128; s >= 1; s >>= 1) {
                int nb = b + s;
                if (nb < NB && s_start[nb] <= e) b = nb;
            }
            const int s0 = s_start[b], s1 = s_start[b + 1];
            const float ui = s_u[e], wi = s_w[e];
            float cross, acc = 0.f;
            if (isexp) {
                cross = wi * s_pU[b] + ui * s_rev[b];
                for (int j = s0; j < s1; ++j)
                    acc += fminf(ui * s_w[j], s_u[j] * wi);
            } else {
                float cb = (float)s0, ca = (float)(N - s1);
                cross = ui * cb - s_pU[b] + s_rev[b] - ui * ca;
                for (int j = s0; j < s1; ++j)
                    acc += fabsf(ui - s_u[j]);
            }
            g_closed[feat][s_idx[e]] = cross + acc;
        }
        return;
    }

    // ================= PAIRWISE BLOCK: sky_sep + mass_sim only =================
    float4* sj = (float4*)(smraw);      // [JC] {ra, dec, mc30, pad}
    const int pb = blockIdx.x - NFEAT;
    const int ib = pb & (NBI - 1);
    const int jb = pb >> 4;
    const int i  = ib * IB + tid;
    const int j0 = jb * JC;

    if (tid < JC) {
        float3 v = pair_inv(p, j0 + tid);
        sj[tid] = make_float4(v.x, v.y, v.z, 0.f);
    }
    float3 a = pair_inv(p, i);
    __syncthreads();

    float s_sky = 0.f, s_ms = 0.f;
    #pragma unroll 8
    for (int j = 0; j < JC; ++j) {
        const float4 b = sj[j];
        float dra = a.x - b.x;
        float dde = a.y - b.y;
        s_sky += f_sqrt(fmaf(dra, dra, dde * dde));
        s_ms  += f_rcp(1.0f + fabsf(a.z - b.z));
    }
    g_part2[jb][i] = make_float2(s_sky, s_ms);
}

// ---------------------------------------------------------------------------
// Finish: 16 lanes per row (2 rows/warp). 256 blocks x 256 threads.
// ---------------------------------------------------------------------------
#define FTB 256
__global__ void __launch_bounds__(FTB) finish_kernel(
    const float* __restrict__ W1, const float* __restrict__ b1,
    const float* __restrict__ ln_g, const float* __restrict__ ln_b,
    const float* __restrict__ W2, const float* __restrict__ b2,
    float* __restrict__ out)
{
    __shared__ float sW1[8 * 32];
    __shared__ float sW2[32 * 16];
    __shared__ float sb1[32], sg[32], sbeta[32], sb2[16];

    for (int k = threadIdx.x; k < 256; k += FTB) sW1[k] = W1[k];
    for (int k = threadIdx.x; k < 512; k += FTB) sW2[k] = W2[k];
    if (threadIdx.x < 32) {
        int k = threadIdx.x;
        sb1[k] = b1[k]; sg[k] = ln_g[k]; sbeta[k] = ln_b[k];
        if (k < 16) sb2[k] = b2[k];
    }
    __syncthreads();

    const int lane = threadIdx.x & 31;
    const int warp = threadIdx.x >> 5;
    const int sub  = lane & 15;           // lane within row-group
    const int rig  = lane >> 4;           // row within warp (0..1)
    const int i    = blockIdx.x * 16 + warp * 2 + rig;

    // reduce pairwise partials: lane sums 2 of 32 chunks, 16-lane butterfly
    float t_sky = 0.f, t_ms = 0.f;
    #pragma unroll
    for (int cc = 0; cc < 2; ++cc) {
        float2 pp = g_part2[sub * 2 + cc][i];
        t_sky += pp.x; t_ms += pp.y;
    }
    #pragma unroll
    for (int m = 1; m < 16; m <<= 1) {
        t_sky += __shfl_xor_sync(0xFFFFFFFFu, t_sky, m);
        t_ms  += __shfl_xor_sync(0xFFFFFFFFu, t_ms,  m);
    }

    const float inv = 1.0f / (float)(N - 1);
    float x[8];
    x[0] = g_closed[0][i] * inv;               // dt
    x[1] = t_sky * inv;                        // sky_sep (self = 0)
    x[2] = (t_ms - 1.0f) * inv;                // mass_sim (self = 1)
    x[3] = (g_closed[4][i] - 1.0f) * inv;      // freq_ov (self ~ 1)
    x[4] = (g_closed[5][i] - 1.0f) * inv;      // dist_ratio (self ~ 1)
    x[5] = g_closed[1][i] * inv;               // dpsi
    x[6] = g_closed[2][i] * inv;               // dra
    x[7] = g_closed[3][i] * inv;               // ddec

    // h = x @ W1 + b1 : lane owns k = sub*2, sub*2+1
    const int k0 = sub * 2;
    float h[2];
    #pragma unroll
    for (int kk = 0; kk < 2; ++kk) {
        float acc = sb1[k0 + kk];
        #pragma unroll
        for (int f = 0; f < 8; ++f)
            acc = fmaf(x[f], sW1[f * 32 + k0 + kk], acc);
        h[kk] = acc;
    }

    // LayerNorm over 32 values spread across 16 lanes
    float s1 = h[0] + h[1];
    #pragma unroll
    for (int m = 1; m < 16; m <<= 1) s1 += __shfl_xor_sync(0xFFFFFFFFu, s1, m);
    float mu = s1 * (1.0f / 32.0f);

    float d0 = h[0] - mu, d1 = h[1] - mu;
    float s2 = fmaf(d0, d0, d1 * d1);
    #pragma unroll
    for (int m = 1; m < 16; m <<= 1) s2 += __shfl_xor_sync(0xFFFFFFFFu, s2, m);
    float rs = rsqrtf(s2 * (1.0f / 32.0f) + 1e-5f);

    // affine + exact GELU (2 erff per lane)
    #pragma unroll
    for (int kk = 0; kk < 2; ++kk) {
        float v = fmaf((h[kk] - mu) * rs, sg[k0 + kk], sbeta[k0 + kk]);
        h[kk] = 0.5f * v * (1.0f + erff(v * 0.7071067811865475f));
    }

    // out = h @ W2 + b2 : partials over lane's 2 k's, 16-lane butterfly
    float o[16];
    #pragma unroll
    for (int oo = 0; oo < 16; ++oo) o[oo] = 0.f;
    #pragma unroll
    for (int kk = 0; kk < 2; ++kk) {
        #pragma unroll
        for (int oo = 0; oo < 16; ++oo)
            o[oo] = fmaf(h[kk], sW2[(k0 + kk) * 16 + oo], o[oo]);
    }
    #pragma unroll
    for (int m = 1; m < 16; m <<= 1) {
        #pragma unroll
        for (int oo = 0; oo < 16; ++oo)
            o[oo] += __shfl_xor_sync(0xFFFFFFFFu, o[oo], m);
    }

    if (sub == 0) {
        float4* op = reinterpret_cast<float4*>(out + i * 16);
        op[0] = make_float4(o[0]  + sb2[0],  o[1]  + sb2[1],
                            o[2]  + sb2[2],  o[3]  + sb2[3]);
        op[1] = make_float4(o[4]  + sb2[4],  o[5]  + sb2[5],
                            o[6]  + sb2[6],  o[7]  + sb2[7]);
        op[2] = make_float4(o[8]  + sb2[8],  o[9]  + sb2[9],
                            o[10] + sb2[10], o[11] + sb2[11]);
        op[3] = make_float4(o[12] + sb2[12], o[13] + sb2[13],
                            o[14] + sb2[14], o[15] + sb2[15]);
    }
}

extern "C" void kernel_launch(void* const* d_in, const int* in_sizes, int n_in,
                              void* d_out, int out_size) {
    const float* params = (const float*)d_in[0];
    const float* W1     = (const float*)d_in[1];
    const float* b1     = (const float*)d_in[2];
    const float* ln_g   = (const float*)d_in[3];
    const float* ln_b   = (const float*)d_in[4];
    const float* W2     = (const float*)d_in[5];
    const float* b2     = (const float*)d_in[6];
    float* out = (float*)d_out;

    fused_kernel<<<NFEAT + NBI * NJ, IB>>>(params);
    finish_kernel<<<N / 16, FTB>>>(W1, b1, ln_g, ln_b, W2, b2, out);
}

// round 9
// speedup vs baseline: 1.9811x; 1.6132x over previous
#include <cuda_runtime.h>

#define N      4096
#define NFEAT  6
#define NB     4096          // fine value-buckets per feature
#define IB     256           // threads per block
#define NBI    8             // i-blocks (512 i each, 2 per thread)
#define NJ     64            // j-chunks
#define JC     64            // j per chunk

// Pairwise partials (sky_sep, mass_sim) per j-chunk
__device__ float2 g_part2[NJ][N];
// Closed-form per-row sums: 0=dt 1=dpsi 2=dra 3=ddec 4=freq_ov 5=dist_ratio
__device__ float  g_closed[NFEAT][N];

__device__ __forceinline__ float f_ex2(float x) {
    float r; asm("ex2.approx.ftz.f32 %0, %1;" : "=f"(r) : "f"(x)); return r;
}
__device__ __forceinline__ float f_lg2(float x) {
    float r; asm("lg2.approx.ftz.f32 %0, %1;" : "=f"(r) : "f"(x)); return r;
}
__device__ __forceinline__ float f_rcp(float x) {
    float r; asm("rcp.approx.ftz.f32 %0, %1;" : "=f"(r) : "f"(x)); return r;
}
__device__ __forceinline__ float f_sqrt(float x) {
    float r; asm("sqrt.approx.ftz.f32 %0, %1;" : "=f"(r) : "f"(x)); return r;
}

// pairwise needs (ra, dec, mc30)
__device__ __forceinline__ float3 pair_inv(const float* __restrict__ p, int idx) {
    const float* q = p + idx * 15;
    float m1 = q[0] * 95.0f + 5.0f;
    float m2 = q[1] * 95.0f + 5.0f;
    float mc = f_ex2(0.6f * f_lg2(m1 * m2) - 0.2f * f_lg2(m1 + m2));
    return make_float3(q[3], q[4], mc * (1.0f / 30.0f));
}

// key (bucket variable), u, w per feature.
//   abs features (0-3): key in [0,1), u = key, w unused
//   feat 4 (freq_ov):   x = (220/msum)*log2e/100; u = 2^x, w = 2^-x
//                       pair term: below(xj<xi): wi*uj = 2^{xj-xi}; above: ui*wj
//   feat 5 (dist_ratio):key = log2(D); u = D, w = 1/D
//                       below(Dj<Di): wi*uj = Dj/Di; above: ui*wj = Di/Dj
__device__ __forceinline__ void feat_vals(const float* __restrict__ p, int e, int feat,
                                          float& key, float& u, float& w) {
    const float* q = p + e * 15;
    if (feat == 0)      { key = q[5]; u = key; w = 0.f; }
    else if (feat == 1) { key = q[7]; u = key; w = 0.f; }
    else if (feat == 2) { key = q[3]; u = key; w = 0.f; }
    else if (feat == 3) { key = q[4]; u = key; w = 0.f; }
    else if (feat == 4) {
        float msum = (q[0] + q[1]) * 95.0f + 10.0f;
        const float C = 3.1739290899557192f;          // 220*log2(e)/100
        float x = C * f_rcp(msum);
        key = x; u = f_ex2(x); w = f_ex2(-x);
    } else {
        float d = q[2] * 2950.0f + 50.0f;
        key = f_lg2(d); u = d; w = f_rcp(d);
    }
}

// exclusive prefix over 256 thread-values (tid order); all threads call.
__device__ __forceinline__ float excl_scan256(float val, float* warpTmp) {
    const int lane = threadIdx.x & 31, wid = threadIdx.x >> 5;
    float incl = val;
    #pragma unroll
    for (int off = 1; off < 32; off <<= 1) {
        float t = __shfl_up_sync(0xFFFFFFFFu, incl, off);
        if (lane >= off) incl += t;
    }
    __syncthreads();
    if (lane == 31) warpTmp[wid] = incl;
    __syncthreads();
    float base = 0.f;
    #pragma unroll
    for (int ww = 0; ww < 8; ++ww)
        base += (ww < wid) ? warpTmp[ww] : 0.f;
    return base + incl - val;
}

// in-place inclusive scan of arr[NB] with 256 threads (16 per thread)
__device__ __forceinline__ void incl_scan4096(float* arr, float* warpTmp) {
    const int base = threadIdx.x * 16;
    float seg = 0.f;
    #pragma unroll
    for (int q = 0; q < 16; ++q) seg += arr[base + q];
    float run = excl_scan256(seg, warpTmp);
    #pragma unroll
    for (int q = 0; q < 16; ++q) { run += arr[base + q]; arr[base + q] = run; }
}

// smem: two NB float arrays + scan temp; pairwise path aliases the front.
#define SMEM_SZ (NB * 8 + 64)

__global__ void __launch_bounds__(IB) fused_kernel(const float* __restrict__ p) {
    __shared__ __align__(16) unsigned char smraw[SMEM_SZ];
    const int tid = threadIdx.x;

    if (blockIdx.x < NFEAT) {
        // ============ FEATURE BLOCK: O(1)-per-element bucketed closed form ============
        const int feat = blockIdx.x;
        const bool isexp = (feat >= 4);
        float* sA = (float*)(smraw);             // abs: incl count | exp: incl U
        float* sB = (float*)(smraw + NB * 4);    // abs: incl U     | exp: incl W
        float* warpTmp = (float*)(smraw + NB * 8);

        float lo, scale;
        if      (feat == 4) { lo = 0.01580f; scale = (float)NB / 0.30220f; }
        else if (feat == 5) { lo = 5.64350f; scale = (float)NB / 5.91200f; }
        else                { lo = 0.0f;     scale = (float)NB; }

        #pragma unroll
        for (int q = tid; q < NB; q += IB) { sA[q] = 0.f; sB[q] = 0.f; }
        __syncthreads();

        // pass 1: histogram + aggregates (spread smem atomics)
        for (int e = tid; e < N; e += IB) {
            float key, u, w; feat_vals(p, e, feat, key, u, w);
            int b = min(NB - 1, max(0, (int)((key - lo) * scale)));
            if (isexp) { atomicAdd(&sA[b], u); atomicAdd(&sB[b], w); }
            else       { atomicAdd(&sA[b], 1.0f); atomicAdd(&sB[b], u); }
        }
        __syncthreads();

        // inclusive scans in place
        incl_scan4096(sA, warpTmp);
        __syncthreads();
        incl_scan4096(sB, warpTmp);
        __syncthreads();

        const float TotA = sA[NB - 1];
        const float TotB = sB[NB - 1];

        // pass 2: O(1) closed form per element (self excluded exactly)
        for (int e = tid; e < N; e += IB) {
            float key, u, w; feat_vals(p, e, feat, key, u, w);
            int b = min(NB - 1, max(0, (int)((key - lo) * scale)));
            float res;
            if (isexp) {
                // below (incl same-bucket minus self): w_i * (inclU - u)
                // above: u_i * (TotW - inclW)
                res = w * (sA[b] - u) + u * (TotB - sB[b]);
            } else {
                float cb = sA[b] - 1.0f;          // below count (same-bucket as below)
                float ca = (float)N - sA[b];      // above count
                res = u * cb - (sB[b] - u) + (TotB - sB[b]) - u * ca;
            }
            g_closed[feat][e] = res;
        }
        (void)TotA;
        return;
    }

    // ============ PAIRWISE BLOCK: sky_sep + mass_sim, 2-way i-tiling ============
    float4* sj = (float4*)(smraw);      // [JC] {ra, dec, mc30, pad}
    const int pb = blockIdx.x - NFEAT;
    const int ib = pb & (NBI - 1);
    const int jb = pb >> 3;             // NBI = 8
    const int i0 = ib * 512 + tid;
    const int i1 = i0 + 256;
    const int j0 = jb * JC;

    if (tid < JC) {
        float3 v = pair_inv(p, j0 + tid);
        sj[tid] = make_float4(v.x, v.y, v.z, 0.f);
    }
    float3 a0 = pair_inv(p, i0);
    float3 a1 = pair_inv(p, i1);
    __syncthreads();

    float sky0 = 0.f, ms0 = 0.f, sky1 = 0.f, ms1 = 0.f;
    #pragma unroll 8
    for (int j = 0; j < JC; ++j) {
        const float4 b = sj[j];
        float dra0 = a0.x - b.x, dde0 = a0.y - b.y;
        float dra1 = a1.x - b.x, dde1 = a1.y - b.y;
        sky0 += f_sqrt(fmaf(dra0, dra0, dde0 * dde0));
        sky1 += f_sqrt(fmaf(dra1, dra1, dde1 * dde1));
        ms0  += f_rcp(1.0f + fabsf(a0.z - b.z));
        ms1  += f_rcp(1.0f + fabsf(a1.z - b.z));
    }
    g_part2[jb][i0] = make_float2(sky0, ms0);
    g_part2[jb][i1] = make_float2(sky1, ms1);
}

// ---------------------------------------------------------------------------
// Finish: 8 lanes per row (R4-proven layout). 128 blocks x 256 threads.
// ---------------------------------------------------------------------------
#define FTB 256
__global__ void __launch_bounds__(FTB) finish_kernel(
    const float* __restrict__ W1, const float* __restrict__ b1,
    const float* __restrict__ ln_g, const float* __restrict__ ln_b,
    const float* __restrict__ W2, const float* __restrict__ b2,
    float* __restrict__ out)
{
    __shared__ float sW1[8 * 32];
    __shared__ float sW2[32 * 16];
    __shared__ float sb1[32], sg[32], sbeta[32], sb2[16];

    for (int k = threadIdx.x; k < 256; k += FTB) sW1[k] = W1[k];
    for (int k = threadIdx.x; k < 512; k += FTB) sW2[k] = W2[k];
    if (threadIdx.x < 32) {
        int k = threadIdx.x;
        sb1[k] = b1[k]; sg[k] = ln_g[k]; sbeta[k] = ln_b[k];
        if (k < 16) sb2[k] = b2[k];
    }
    __syncthreads();

    const int lane = threadIdx.x & 31;
    const int warp = threadIdx.x >> 5;
    const int sub  = lane & 7;          // lane within row-group (0..7)
    const int rig  = lane >> 3;         // row within warp (0..3)
    const int i    = blockIdx.x * 32 + warp * 4 + rig;

    // reduce pairwise partials: lane sums 8 of 64 chunks, butterfly over 8 lanes
    float t_sky = 0.f, t_ms = 0.f;
    #pragma unroll
    for (int cc = 0; cc < 8; ++cc) {
        float2 pp = g_part2[sub * 8 + cc][i];
        t_sky += pp.x; t_ms += pp.y;
    }
    #pragma unroll
    for (int m = 1; m < 8; m <<= 1) {
        t_sky += __shfl_xor_sync(0xFFFFFFFFu, t_sky, m);
        t_ms  += __shfl_xor_sync(0xFFFFFFFFu, t_ms,  m);
    }

    const float inv = 1.0f / (float)(N - 1);
    float x[8];
    x[0] = g_closed[0][i] * inv;             // dt        (self excluded)
    x[1] = t_sky * inv;                      // sky_sep   (self term = 0)
    x[2] = (t_ms - 1.0f) * inv;              // mass_sim  (self term = 1)
    x[3] = g_closed[4][i] * inv;             // freq_ov   (self excluded)
    x[4] = g_closed[5][i] * inv;             // dist_ratio(self excluded)
    x[5] = g_closed[1][i] * inv;             // dpsi
    x[6] = g_closed[2][i] * inv;             // dra
    x[7] = g_closed[3][i] * inv;             // ddec

    // h = x @ W1 + b1 : lane owns k = sub*4 .. sub*4+3
    const int k0 = sub * 4;
    float h[4];
    #pragma unroll
    for (int kk = 0; kk < 4; ++kk) {
        float acc = sb1[k0 + kk];
        #pragma unroll
        for (int f = 0; f < 8; ++f)
            acc = fmaf(x[f], sW1[f * 32 + k0 + kk], acc);
        h[kk] = acc;
    }

    // LayerNorm over 32 values across 8 lanes
    float s1 = h[0] + h[1] + h[2] + h[3];
    #pragma unroll
    for (int m = 1; m < 8; m <<= 1) s1 += __shfl_xor_sync(0xFFFFFFFFu, s1, m);
    float mu = s1 * (1.0f / 32.0f);

    float s2 = 0.f;
    #pragma unroll
    for (int kk = 0; kk < 4; ++kk) {
        float d = h[kk] - mu;
        s2 = fmaf(d, d, s2);
    }
    #pragma unroll
    for (int m = 1; m < 8; m <<= 1) s2 += __shfl_xor_sync(0xFFFFFFFFu, s2, m);
    float rs = rsqrtf(s2 * (1.0f / 32.0f) + 1e-5f);

    // affine + exact GELU (4 erff per lane)
    #pragma unroll
    for (int kk = 0; kk < 4; ++kk) {
        float v = fmaf((h[kk] - mu) * rs, sg[k0 + kk], sbeta[k0 + kk]);
        h[kk] = 0.5f * v * (1.0f + erff(v * 0.7071067811865475f));
    }

    // out = h @ W2 + b2 : partials over lane's 4 k's, butterfly
    float o[16];
    #pragma unroll
    for (int oo = 0; oo < 16; ++oo) o[oo] = 0.f;
    #pragma unroll
    for (int kk = 0; kk < 4; ++kk) {
        #pragma unroll
        for (int oo = 0; oo < 16; ++oo)
            o[oo] = fmaf(h[kk], sW2[(k0 + kk) * 16 + oo], o[oo]);
    }
    #pragma unroll
    for (int m = 1; m < 8; m <<= 1) {
        #pragma unroll
        for (int oo = 0; oo < 16; ++oo)
            o[oo] += __shfl_xor_sync(0xFFFFFFFFu, o[oo], m);
    }

    if (sub == 0) {
        float4* op = reinterpret_cast<float4*>(out + i * 16);
        op[0] = make_float4(o[0]  + sb2[0],  o[1]  + sb2[1],
                            o[2]  + sb2[2],  o[3]  + sb2[3]);
        op[1] = make_float4(o[4]  + sb2[4],  o[5]  + sb2[5],
                            o[6]  + sb2[6],  o[7]  + sb2[7]);
        op[2] = make_float4(o[8]  + sb2[8],  o[9]  + sb2[9],
                            o[10] + sb2[10], o[11] + sb2[11]);
        op[3] = make_float4(o[12] + sb2[12], o[13] + sb2[13],
                            o[14] + sb2[14], o[15] + sb2[15]);
    }
}

extern "C" void kernel_launch(void* const* d_in, const int* in_sizes, int n_in,
                              void* d_out, int out_size) {
    const float* params = (const float*)d_in[0];
    const float* W1     = (const float*)d_in[1];
    const float* b1     = (const float*)d_in[2];
    const float* ln_g   = (const float*)d_in[3];
    const float* ln_b   = (const float*)d_in[4];
    const float* W2     = (const float*)d_in[5];
    const float* b2     = (const float*)d_in[6];
    float* out = (float*)d_out;

    fused_kernel<<<NFEAT + NBI * NJ, IB>>>(params);
    finish_kernel<<<N / 32, FTB>>>(W1, b1, ln_g, ln_b, W2, b2, out);
}

// round 10
// speedup vs baseline: 2.1429x; 1.0816x over previous
#include <cuda_runtime.h>

#define N      4096
#define NFEAT  6
#define NB     4096          // fine value-buckets per feature
#define IB     256           // threads per block
#define NBI    8             // i-blocks (512 i each, 2 per thread)
#define NJ     64            // j-chunks
#define JC     64            // j per chunk

// Pairwise partials (sky_sep, mass_sim) per j-chunk
__device__ float2 g_part2[NJ][N];
// Closed-form per-row sums: 0=dt 1=dpsi 2=dra 3=ddec 4=freq_ov 5=dist_ratio
__device__ float  g_closed[NFEAT][N];
// Precomputed per-element data (coalesced layouts)
__device__ float4 g_pi[N];   // {ra, dec, mc30, -}
__device__ float4 g_ab[N];   // {t, psi, ra, dec}       (abs-feature keys)
__device__ float4 g_e4[N];   // {x, 2^x, 2^-x, L}       (freq_ov + dist key)
__device__ float2 g_e5[N];   // {d, 1/d}                (dist_ratio u,w)

__device__ __forceinline__ float f_ex2(float x) {
    float r; asm("ex2.approx.ftz.f32 %0, %1;" : "=f"(r) : "f"(x)); return r;
}
__device__ __forceinline__ float f_lg2(float x) {
    float r; asm("lg2.approx.ftz.f32 %0, %1;" : "=f"(r) : "f"(x)); return r;
}
__device__ __forceinline__ float f_rcp(float x) {
    float r; asm("rcp.approx.ftz.f32 %0, %1;" : "=f"(r) : "f"(x)); return r;
}
__device__ __forceinline__ float f_sqrt(float x) {
    float r; asm("sqrt.approx.ftz.f32 %0, %1;" : "=f"(r) : "f"(x)); return r;
}

// ---------------------------------------------------------------------------
// Kernel A: per-element invariants, written coalesced. 16 blocks x 256.
// ---------------------------------------------------------------------------
__global__ void __launch_bounds__(IB) prep_kernel(const float* __restrict__ p) {
    const int e = blockIdx.x * IB + threadIdx.x;
    const float* q = p + e * 15;
    float p0 = q[0], p1 = q[1], p2 = q[2];
    float p3 = q[3], p4 = q[4], p5 = q[5], p7 = q[7];

    float m1 = p0 * 95.0f + 5.0f;
    float m2 = p1 * 95.0f + 5.0f;
    float msum = m1 + m2;
    float mc = f_ex2(0.6f * f_lg2(m1 * m2) - 0.2f * f_lg2(msum));
    const float C = 3.1739290899557192f;   // 220*log2(e)/100
    float x = C * f_rcp(msum);
    float d = p2 * 2950.0f + 50.0f;

    g_pi[e] = make_float4(p3, p4, mc * (1.0f / 30.0f), 0.f);
    g_ab[e] = make_float4(p5, p7, p3, p4);
    g_e4[e] = make_float4(x, f_ex2(x), f_ex2(-x), f_lg2(d));
    g_e5[e] = make_float2(d, f_rcp(d));
}

// exclusive prefix over 256 thread-values (tid order); all threads call.
__device__ __forceinline__ float excl_scan256(float val, float* warpTmp) {
    const int lane = threadIdx.x & 31, wid = threadIdx.x >> 5;
    float incl = val;
    #pragma unroll
    for (int off = 1; off < 32; off <<= 1) {
        float t = __shfl_up_sync(0xFFFFFFFFu, incl, off);
        if (lane >= off) incl += t;
    }
    __syncthreads();
    if (lane == 31) warpTmp[wid] = incl;
    __syncthreads();
    float base = 0.f;
    #pragma unroll
    for (int ww = 0; ww < 8; ++ww)
        base += (ww < wid) ? warpTmp[ww] : 0.f;
    return base + incl - val;
}

// in-place inclusive scan of arr[NB] with 256 threads (16 per thread)
__device__ __forceinline__ void incl_scan4096(float* arr, float* warpTmp) {
    const int base = threadIdx.x * 16;
    float seg = 0.f;
    #pragma unroll
    for (int q = 0; q < 16; ++q) seg += arr[base + q];
    float run = excl_scan256(seg, warpTmp);
    #pragma unroll
    for (int q = 0; q < 16; ++q) { run += arr[base + q]; arr[base + q] = run; }
}

#define SMEM_SZ (NB * 8 + 64)

// per-feature (key, u, w) from the packed arrays — coalesced vector loads
__device__ __forceinline__ void feat_vals_fast(int e, int feat,
                                               float& key, float& u, float& w) {
    if (feat < 4) {
        float4 ab = g_ab[e];
        key = (feat == 0) ? ab.x : (feat == 1) ? ab.y : (feat == 2) ? ab.z : ab.w;
        u = key; w = 0.f;
    } else if (feat == 4) {
        float4 e4 = g_e4[e];
        key = e4.x; u = e4.y; w = e4.z;
    } else {
        float4 e4 = g_e4[e];
        float2 e5 = g_e5[e];
        key = e4.w; u = e5.x; w = e5.y;
    }
}

// ---------------------------------------------------------------------------
// Kernel B: 6 feature blocks (bucketed closed form) + 512 pairwise blocks.
// ---------------------------------------------------------------------------
__global__ void __launch_bounds__(IB) fused_kernel() {
    __shared__ __align__(16) unsigned char smraw[SMEM_SZ];
    const int tid = threadIdx.x;

    if (blockIdx.x < NFEAT) {
        const int feat = blockIdx.x;
        const bool isexp = (feat >= 4);
        float* sA = (float*)(smraw);             // abs: incl count | exp: incl U
        float* sB = (float*)(smraw + NB * 4);    // abs: incl U     | exp: incl W
        float* warpTmp = (float*)(smraw + NB * 8);

        float lo, scale;
        if      (feat == 4) { lo = 0.01580f; scale = (float)NB / 0.30220f; }
        else if (feat == 5) { lo = 5.64350f; scale = (float)NB / 5.91200f; }
        else                { lo = 0.0f;     scale = (float)NB; }

        #pragma unroll
        for (int q = tid; q < NB; q += IB) { sA[q] = 0.f; sB[q] = 0.f; }
        __syncthreads();

        // pass 1: histogram + aggregates (coalesced reads, spread smem atomics)
        #pragma unroll
        for (int e = tid; e < N; e += IB) {
            float key, u, w; feat_vals_fast(e, feat, key, u, w);
            int b = min(NB - 1, max(0, (int)((key - lo) * scale)));
            if (isexp) { atomicAdd(&sA[b], u); atomicAdd(&sB[b], w); }
            else       { atomicAdd(&sA[b], 1.0f); atomicAdd(&sB[b], u); }
        }
        __syncthreads();

        incl_scan4096(sA, warpTmp);
        __syncthreads();
        incl_scan4096(sB, warpTmp);
        __syncthreads();

        const float TotB = sB[NB - 1];

        // pass 2: O(1) closed form per element (self excluded exactly)
        #pragma unroll
        for (int e = tid; e < N; e += IB) {
            float key, u, w; feat_vals_fast(e, feat, key, u, w);
            int b = min(NB - 1, max(0, (int)((key - lo) * scale)));
            float res;
            if (isexp) {
                res = w * (sA[b] - u) + u * (TotB - sB[b]);
            } else {
                float cb = sA[b] - 1.0f;
                float ca = (float)N - sA[b];
                res = u * cb - (sB[b] - u) + (TotB - sB[b]) - u * ca;
            }
            g_closed[feat][e] = res;
        }
        return;
    }

    // ============ PAIRWISE BLOCK: sky_sep + mass_sim, 2-way i-tiling ============
    float4* sj = (float4*)(smraw);      // [JC] {ra, dec, mc30, pad}
    const int pb = blockIdx.x - NFEAT;
    const int ib = pb & (NBI - 1);
    const int jb = pb >> 3;             // NBI = 8
    const int i0 = ib * 512 + tid;
    const int i1 = i0 + 256;
    const int j0 = jb * JC;

    if (tid < JC) sj[tid] = g_pi[j0 + tid];
    float4 a0 = g_pi[i0];
    float4 a1 = g_pi[i1];
    __syncthreads();

    float sky0 = 0.f, ms0 = 0.f, sky1 = 0.f, ms1 = 0.f;
    #pragma unroll 8
    for (int j = 0; j < JC; ++j) {
        const float4 b = sj[j];
        float dra0 = a0.x - b.x, dde0 = a0.y - b.y;
        float dra1 = a1.x - b.x, dde1 = a1.y - b.y;
        sky0 += f_sqrt(fmaf(dra0, dra0, dde0 * dde0));
        sky1 += f_sqrt(fmaf(dra1, dra1, dde1 * dde1));
        ms0  += f_rcp(1.0f + fabsf(a0.z - b.z));
        ms1  += f_rcp(1.0f + fabsf(a1.z - b.z));
    }
    g_part2[jb][i0] = make_float2(sky0, ms0);
    g_part2[jb][i1] = make_float2(sky1, ms1);
}

// ---------------------------------------------------------------------------
// Finish: 8 lanes per row. 128 blocks x 256 threads.
// ---------------------------------------------------------------------------
#define FTB 256
__global__ void __launch_bounds__(FTB) finish_kernel(
    const float* __restrict__ W1, const float* __restrict__ b1,
    const float* __restrict__ ln_g, const float* __restrict__ ln_b,
    const float* __restrict__ W2, const float* __restrict__ b2,
    float* __restrict__ out)
{
    __shared__ float sW1[8 * 32];
    __shared__ float sW2[32 * 16];
    __shared__ float sb1[32], sg[32], sbeta[32], sb2[16];

    for (int k = threadIdx.x; k < 256; k += FTB) sW1[k] = W1[k];
    for (int k = threadIdx.x; k < 512; k += FTB) sW2[k] = W2[k];
    if (threadIdx.x < 32) {
        int k = threadIdx.x;
        sb1[k] = b1[k]; sg[k] = ln_g[k]; sbeta[k] = ln_b[k];
        if (k < 16) sb2[k] = b2[k];
    }
    __syncthreads();

    const int lane = threadIdx.x & 31;
    const int warp = threadIdx.x >> 5;
    const int sub  = lane & 7;
    const int rig  = lane >> 3;
    const int i    = blockIdx.x * 32 + warp * 4 + rig;

    float t_sky = 0.f, t_ms = 0.f;
    #pragma unroll
    for (int cc = 0; cc < 8; ++cc) {
        float2 pp = g_part2[sub * 8 + cc][i];
        t_sky += pp.x; t_ms += pp.y;
    }
    #pragma unroll
    for (int m = 1; m < 8; m <<= 1) {
        t_sky += __shfl_xor_sync(0xFFFFFFFFu, t_sky, m);
        t_ms  += __shfl_xor_sync(0xFFFFFFFFu, t_ms,  m);
    }

    const float inv = 1.0f / (float)(N - 1);
    float x[8];
    x[0] = g_closed[0][i] * inv;
    x[1] = t_sky * inv;
    x[2] = (t_ms - 1.0f) * inv;
    x[3] = g_closed[4][i] * inv;
    x[4] = g_closed[5][i] * inv;
    x[5] = g_closed[1][i] * inv;
    x[6] = g_closed[2][i] * inv;
    x[7] = g_closed[3][i] * inv;

    const int k0 = sub * 4;
    float h[4];
    #pragma unroll
    for (int kk = 0; kk < 4; ++kk) {
        float acc = sb1[k0 + kk];
        #pragma unroll
        for (int f = 0; f < 8; ++f)
            acc = fmaf(x[f], sW1[f * 32 + k0 + kk], acc);
        h[kk] = acc;
    }

    float s1 = h[0] + h[1] + h[2] + h[3];
    #pragma unroll
    for (int m = 1; m < 8; m <<= 1) s1 += __shfl_xor_sync(0xFFFFFFFFu, s1, m);
    float mu = s1 * (1.0f / 32.0f);

    float s2 = 0.f;
    #pragma unroll
    for (int kk = 0; kk < 4; ++kk) {
        float d = h[kk] - mu;
        s2 = fmaf(d, d, s2);
    }
    #pragma unroll
    for (int m = 1; m < 8; m <<= 1) s2 += __shfl_xor_sync(0xFFFFFFFFu, s2, m);
    float rs = rsqrtf(s2 * (1.0f / 32.0f) + 1e-5f);

    #pragma unroll
    for (int kk = 0; kk < 4; ++kk) {
        float v = fmaf((h[kk] - mu) * rs, sg[k0 + kk], sbeta[k0 + kk]);
        h[kk] = 0.5f * v * (1.0f + erff(v * 0.7071067811865475f));
    }

    float o[16];
    #pragma unroll
    for (int oo = 0; oo < 16; ++oo) o[oo] = 0.f;
    #pragma unroll
    for (int kk = 0; kk < 4; ++kk) {
        #pragma unroll
        for (int oo = 0; oo < 16; ++oo)
            o[oo] = fmaf(h[kk], sW2[(k0 + kk) * 16 + oo], o[oo]);
    }
    #pragma unroll
    for (int m = 1; m < 8; m <<= 1) {
        #pragma unroll
        for (int oo = 0; oo < 16; ++oo)
            o[oo] += __shfl_xor_sync(0xFFFFFFFFu, o[oo], m);
    }

    if (sub == 0) {
        float4* op = reinterpret_cast<float4*>(out + i * 16);
        op[0] = make_float4(o[0]  + sb2[0],  o[1]  + sb2[1],
                            o[2]  + sb2[2],  o[3]  + sb2[3]);
        op[1] = make_float4(o[4]  + sb2[4],  o[5]  + sb2[5],
                            o[6]  + sb2[6],  o[7]  + sb2[7]);
        op[2] = make_float4(o[8]  + sb2[8],  o[9]  + sb2[9],
                            o[10] + sb2[10], o[11] + sb2[11]);
        op[3] = make_float4(o[12] + sb2[12], o[13] + sb2[13],
                            o[14] + sb2[14], o[15] + sb2[15]);
    }
}

extern "C" void kernel_launch(void* const* d_in, const int* in_sizes, int n_in,
                              void* d_out, int out_size) {
    const float* params = (const float*)d_in[0];
    const float* W1     = (const float*)d_in[1];
    const float* b1     = (const float*)d_in[2];
    const float* ln_g   = (const float*)d_in[3];
    const float* ln_b   = (const float*)d_in[4];
    const float* W2     = (const float*)d_in[5];
    const float* b2     = (const float*)d_in[6];
    float* out = (float*)d_out;

    prep_kernel<<<N / IB, IB>>>(params);
    fused_kernel<<<NFEAT + NBI * NJ, IB>>>();
    finish_kernel<<<N / 32, FTB>>>(W1, b1, ln_g, ln_b, W2, b2, out);
}